// round 7
// baseline (speedup 1.0000x reference)
#include <cuda_runtime.h>
#include <cuda_bf16.h>
#include <cstdint>

// Problem constants (shapes are fixed for this problem instance)
#define D 128          // feature dim
#define H 16           // hidden dim
#define NMAX 100000    // max nodes (scratch sizing)

// Scratch: per-node projections P[n][k], k in [0,16) = z[n] @ W1[0:128,:],
// k in [16,32) = z[n] @ W1[128:256,:].  100000*32*4B = 12.8 MB.
__device__ float g_P[(size_t)NMAX * 32];

// ---------------------------------------------------------------------------
// Kernel 1: P = [z @ W1a , z @ W1b]   ([N,128] x [128,32])
// Block = 256 threads = 8 warps. Each warp computes 4 nodes x 32 outputs
// (lane = output k, 4 accumulators per lane). W1 staged transposed+padded in
// smem (conflict-free float4 reads), z tile (32 rows) staged in smem.
// ---------------------------------------------------------------------------
__global__ __launch_bounds__(256) void proj_kernel(
    const float* __restrict__ z,
    const float* __restrict__ W1,
    int N)
{
    __shared__ float zs[32 * D];        // 16 KB
    __shared__ float ws[32 * 132];      // 16.9 KB, row pad 4 -> conflict-free

    const int tid = threadIdx.x;
    const int nb  = blockIdx.x * 32;    // first node of this block

    // Stage W1 transposed: ws[k][d] = W1a[d][k] (k<16) or W1b[d][k-16]
    for (int idx = tid; idx < 32 * D; idx += 256) {
        int k = idx >> 7;
        int d = idx & (D - 1);
        float v = (k < 16) ? W1[d * H + k] : W1[(D + d) * H + (k - 16)];
        ws[k * 132 + d] = v;
    }

    // Stage 32 z rows (vectorized, coalesced)
    {
        const float4* zg = (const float4*)(z + (size_t)nb * D);
        float4* zs4 = (float4*)zs;
        for (int idx = tid; idx < 32 * (D / 4); idx += 256) {
            int r = idx >> 5;           // local row
            if (nb + r < N) zs4[idx] = zg[idx];
        }
    }
    __syncthreads();

    const int lane = tid & 31;          // output index k
    const int warp = tid >> 5;          // node group
    const int n0   = warp * 4;          // local base node

    float acc0 = 0.f, acc1 = 0.f, acc2 = 0.f, acc3 = 0.f;
    const float4* wrow = (const float4*)(ws + lane * 132);
    const float4* z0 = (const float4*)(zs + (n0 + 0) * D);
    const float4* z1 = (const float4*)(zs + (n0 + 1) * D);
    const float4* z2 = (const float4*)(zs + (n0 + 2) * D);
    const float4* z3 = (const float4*)(zs + (n0 + 3) * D);

    #pragma unroll 8
    for (int d4 = 0; d4 < D / 4; d4++) {
        float4 w = wrow[d4];
        float4 a = z0[d4];
        acc0 += a.x * w.x + a.y * w.y + a.z * w.z + a.w * w.w;
        float4 b = z1[d4];
        acc1 += b.x * w.x + b.y * w.y + b.z * w.z + b.w * w.w;
        float4 c = z2[d4];
        acc2 += c.x * w.x + c.y * w.y + c.z * w.z + c.w * w.w;
        float4 e = z3[d4];
        acc3 += e.x * w.x + e.y * w.y + e.z * w.z + e.w * w.w;
    }

    // Write P (32 consecutive floats per node -> coalesced per warp)
    int n = nb + n0;
    if (n + 0 < N) g_P[(size_t)(n + 0) * 32 + lane] = acc0;
    if (n + 1 < N) g_P[(size_t)(n + 1) * 32 + lane] = acc1;
    if (n + 2 < N) g_P[(size_t)(n + 2) * 32 + lane] = acc2;
    if (n + 3 < N) g_P[(size_t)(n + 3) * 32 + lane] = acc3;
}

// ---------------------------------------------------------------------------
// Kernel 2: per-edge. One warp per edge.
//   adj_logits[e] = dot(z[row], z[col])            (128-dim, 4 per lane)
//   h_j = relu(P[row][j] + P[col][16+j] + b1[j])   (lanes 0..15)
//   weights[e] = softplus(sum_j h_j * W2[j] + b2)
// out[0:E] = adj_logits, out[E:2E] = weights
// NOTE: edge_index is int32 (JAX x64 disabled downgrades int64 -> int32).
// ---------------------------------------------------------------------------
__global__ __launch_bounds__(256) void edge_kernel(
    const float* __restrict__ z,
    const int* __restrict__ ei,
    const float* __restrict__ b1,
    const float* __restrict__ W2,
    const float* __restrict__ b2,
    float* __restrict__ out,
    int E)
{
    const int gw   = (blockIdx.x * blockDim.x + threadIdx.x) >> 5;
    const int lane = threadIdx.x & 31;
    if (gw >= E) return;

    int row = 0, col = 0;
    if (lane == 0) {
        row = __ldg(ei + gw);
        col = __ldg(ei + (size_t)E + gw);
    }
    row = __shfl_sync(0xFFFFFFFFu, row, 0);
    col = __shfl_sync(0xFFFFFFFFu, col, 0);

    // ---- dot product head ----
    const float4* zr = (const float4*)(z + (size_t)row * D);
    const float4* zc = (const float4*)(z + (size_t)col * D);
    float4 a = __ldg(zr + lane);
    float4 b = __ldg(zc + lane);
    float dot = a.x * b.x + a.y * b.y + a.z * b.z + a.w * b.w;
    #pragma unroll
    for (int o = 16; o > 0; o >>= 1)
        dot += __shfl_xor_sync(0xFFFFFFFFu, dot, o);
    if (lane == 0) out[gw] = dot;

    // ---- MLP head ----
    float t = 0.f;
    if (lane < 16) {
        float pa = __ldg(&g_P[(size_t)row * 32 + lane]);
        float pb = __ldg(&g_P[(size_t)col * 32 + 16 + lane]);
        float h  = pa + pb + __ldg(b1 + lane);
        h = fmaxf(h, 0.f);
        t = h * __ldg(W2 + lane);
    }
    #pragma unroll
    for (int o = 8; o > 0; o >>= 1)
        t += __shfl_xor_sync(0xFFFFFFFFu, t, o);
    if (lane == 0) {
        float x = t + __ldg(b2);
        // numerically stable softplus, matches jax.nn.softplus to ~1e-6 rel
        float w = (x > 0.f) ? x + log1pf(expf(-x)) : log1pf(expf(x));
        out[(size_t)E + gw] = w;
    }
}

extern "C" void kernel_launch(void* const* d_in, const int* in_sizes, int n_in,
                              void* d_out, int out_size)
{
    // metadata order: z, edge_index, W1, b1, W2, b2
    const float* z  = (const float*)d_in[0];
    const int*   ei = (const int*)d_in[1];   // int32 (see note above)
    const float* W1 = (const float*)d_in[2];
    const float* b1 = (const float*)d_in[3];
    const float* W2 = (const float*)d_in[4];
    const float* b2 = (const float*)d_in[5];
    float* out = (float*)d_out;

    const int N = in_sizes[0] / D;      // 100000
    const int E = in_sizes[1] / 2;      // 600000

    // Kernel 1: per-node projections (32 nodes / block)
    proj_kernel<<<(N + 31) / 32, 256>>>(z, W1, N);

    // Kernel 2: one warp per edge (8 edges / block)
    edge_kernel<<<(E + 7) / 8, 256>>>(z, ei, b1, W2, b2, out, E);
}

// round 8
// speedup vs baseline: 1.8628x; 1.8628x over previous
#include <cuda_runtime.h>
#include <cuda_bf16.h>
#include <cstdint>

#define D 128          // feature dim
#define H 16           // hidden dim
#define NMAX 100000    // max nodes (scratch sizing)

// Per-node projections P[n][k]: k in [0,16) = z[n] @ W1[0:128,:],
// k in [16,32) = z[n] @ W1[128:256,:] + b1[k-16]  (b1 folded in).
__device__ float g_P[(size_t)NMAX * 32];

// ---------------------------------------------------------------------------
// Kernel 1: P = [z @ W1a , z @ W1b + b1]   ([N,128] x [128,32])
// Block = 128 threads = 4 warps, 32 nodes/block, 8 nodes/warp.
// lane = output k; W1 staged transposed+padded (row pad 4) in smem,
// z tile staged in smem (broadcast reads, conflict-free).
// ---------------------------------------------------------------------------
__global__ __launch_bounds__(128) void proj_kernel(
    const float* __restrict__ z,
    const float* __restrict__ W1,
    const float* __restrict__ b1,
    int N)
{
    __shared__ float zs[32 * D];        // 16 KB
    __shared__ float ws[32 * 132];      // 16.9 KB

    const int tid = threadIdx.x;
    const int nb  = blockIdx.x * 32;

    // Stage W1 transposed: ws[k][d] = W1a[d][k] (k<16) or W1b[d][k-16]
    for (int idx = tid; idx < 32 * D; idx += 128) {
        int k = idx >> 7;
        int d = idx & (D - 1);
        float v = (k < 16) ? W1[d * H + k] : W1[(D + d) * H + (k - 16)];
        ws[k * 132 + d] = v;
    }

    // Stage 32 z rows
    {
        const float4* zg = (const float4*)(z + (size_t)nb * D);
        float4* zs4 = (float4*)zs;
        for (int idx = tid; idx < 32 * (D / 4); idx += 128) {
            int r = idx >> 5;
            if (nb + r < N) zs4[idx] = zg[idx];
        }
    }
    __syncthreads();

    const int lane = tid & 31;          // output index k
    const int warp = tid >> 5;
    const int n0   = warp * 8;          // 8 nodes per warp

    float acc[8];
    #pragma unroll
    for (int j = 0; j < 8; j++) acc[j] = 0.f;

    const float4* wrow = (const float4*)(ws + lane * 132);

    #pragma unroll 4
    for (int d4 = 0; d4 < D / 4; d4++) {
        float4 w = wrow[d4];
        #pragma unroll
        for (int j = 0; j < 8; j++) {
            float4 v = ((const float4*)(zs + (n0 + j) * D))[d4];
            acc[j] += v.x * w.x + v.y * w.y + v.z * w.z + v.w * w.w;
        }
    }

    // Fold b1 into upper half of P
    float bb = (lane >= 16) ? __ldg(b1 + lane - 16) : 0.f;

    #pragma unroll
    for (int j = 0; j < 8; j++) {
        int n = nb + n0 + j;
        if (n < N) g_P[(size_t)n * 32 + lane] = acc[j] + bb;
    }
}

// ---------------------------------------------------------------------------
// Kernel 2: 8 lanes per edge (4 edges per warp).
//   adj_logits[e] = dot(z[row], z[col])          (lane covers 16 floats/row)
//   h_j = relu(P[row][j] + P[col][16+j])         (lane covers 2 of 16 j's)
//   weights[e] = softplus(sum_j h_j * W2[j] + b2)
// out[0:E] = adj_logits, out[E:2E] = weights.  edge_index is int32.
// ---------------------------------------------------------------------------
__global__ __launch_bounds__(256) void edge_kernel(
    const float* __restrict__ z,
    const int* __restrict__ ei,
    const float* __restrict__ W2,
    const float* __restrict__ b2,
    float* __restrict__ out,
    int E)
{
    const int t = blockIdx.x * 256 + threadIdx.x;
    const int e = t >> 3;               // edge id
    const int l = t & 7;                // lane within 8-lane segment
    const bool valid = (e < E);
    const int ec = valid ? e : (E - 1); // clamp for tail (grid usually exact)

    const int row = __ldg(ei + ec);
    const int col = __ldg(ei + (size_t)E + ec);

    // ---- issue all gathers up front ----
    const float4* zr = (const float4*)(z + (size_t)row * D);
    const float4* zc = (const float4*)(z + (size_t)col * D);
    float4 a0 = __ldg(zr + l);
    float4 a1 = __ldg(zr + l + 8);
    float4 a2 = __ldg(zr + l + 16);
    float4 a3 = __ldg(zr + l + 24);
    float4 c0 = __ldg(zc + l);
    float4 c1 = __ldg(zc + l + 8);
    float4 c2 = __ldg(zc + l + 16);
    float4 c3 = __ldg(zc + l + 24);

    float2 pa = *(const float2*)(g_P + (size_t)row * 32 + 2 * l);
    float2 pb = *(const float2*)(g_P + (size_t)col * 32 + 16 + 2 * l);
    float2 w2 = __ldg((const float2*)W2 + l);

    // ---- dot head ----
    float dot = a0.x * c0.x + a0.y * c0.y + a0.z * c0.z + a0.w * c0.w
              + a1.x * c1.x + a1.y * c1.y + a1.z * c1.z + a1.w * c1.w
              + a2.x * c2.x + a2.y * c2.y + a2.z * c2.z + a2.w * c2.w
              + a3.x * c3.x + a3.y * c3.y + a3.z * c3.z + a3.w * c3.w;
    dot += __shfl_xor_sync(0xFFFFFFFFu, dot, 1);
    dot += __shfl_xor_sync(0xFFFFFFFFu, dot, 2);
    dot += __shfl_xor_sync(0xFFFFFFFFu, dot, 4);

    // ---- MLP head (b1 already folded into pb half) ----
    float h0 = fmaxf(pa.x + pb.x, 0.f);
    float h1 = fmaxf(pa.y + pb.y, 0.f);
    float tt = h0 * w2.x + h1 * w2.y;
    tt += __shfl_xor_sync(0xFFFFFFFFu, tt, 1);
    tt += __shfl_xor_sync(0xFFFFFFFFu, tt, 2);
    tt += __shfl_xor_sync(0xFFFFFFFFu, tt, 4);

    if (l == 0 && valid) {
        out[e] = dot;
        float x = tt + __ldg(b2);
        // softplus(x) = max(x,0) + log1p(exp(-|x|))  (branchless, stable)
        float w = fmaxf(x, 0.f) + log1pf(expf(-fabsf(x)));
        out[(size_t)E + e] = w;
    }
}

extern "C" void kernel_launch(void* const* d_in, const int* in_sizes, int n_in,
                              void* d_out, int out_size)
{
    // metadata order: z, edge_index, W1, b1, W2, b2
    const float* z  = (const float*)d_in[0];
    const int*   ei = (const int*)d_in[1];   // int32
    const float* W1 = (const float*)d_in[2];
    const float* b1 = (const float*)d_in[3];
    const float* W2 = (const float*)d_in[4];
    const float* b2 = (const float*)d_in[5];
    float* out = (float*)d_out;

    const int N = in_sizes[0] / D;      // 100000
    const int E = in_sizes[1] / 2;      // 600000

    proj_kernel<<<(N + 31) / 32, 128>>>(z, W1, b1, N);

    // 8 lanes/edge -> 8*E threads
    long long threads = (long long)E * 8;
    int grid = (int)((threads + 255) / 256);
    edge_kernel<<<grid, 256>>>(z, ei, W2, b2, out, E);
}

// round 9
// speedup vs baseline: 2.1943x; 1.1779x over previous
#include <cuda_runtime.h>
#include <cuda_bf16.h>
#include <cstdint>

#define D 128          // feature dim
#define H 16           // hidden dim
#define NMAX 100000    // max nodes (scratch sizing)

// Per-node projections P[n][k]: k in [0,16) = z[n] @ W1[0:128,:],
// k in [16,32) = z[n] @ W1[128:256,:] + b1[k-16]  (b1 folded in).
__device__ float g_P[(size_t)NMAX * 32];

// ---------------------------------------------------------------------------
// Kernel 1: P = [z @ W1a , z @ W1b + b1]
// Block = 256 threads = 8 warps; 128 nodes/block, 16 nodes/warp.
// lane = output k.  W staged as wt4[d4][k] (float4 over d, contiguous in k ->
// conflict-free LDS.128).  z staged row-major (main-loop reads are uniform
// broadcasts -> conflict-free).  Inner product uses packed fma.rn.f32x2
// (Blackwell FFMA2): 2 MACs/inst, pairs taken along d so operands are
// register-adjacent halves of float4 loads (no packing cost).
// Dynamic smem: zs 64KB + wt4 16KB = 80KB.
// ---------------------------------------------------------------------------
__global__ __launch_bounds__(256) void proj_kernel(
    const float* __restrict__ z,
    const float* __restrict__ W1,
    const float* __restrict__ b1,
    int N)
{
    extern __shared__ float smem[];
    float*  zs  = smem;                       // [128][128]
    float4* wt4 = (float4*)(smem + 128 * D);  // [32 d4][32 k]

    const int tid = threadIdx.x;
    const int nb  = blockIdx.x * 128;

    // Stage W transposed+vectorized: wt4[d4*32 + k] = (w(k,4d4..4d4+3))
    // where w(k,d) = W1a[d][k] for k<16, W1b[d][k-16] for k>=16.
    for (int idx = tid; idx < 32 * 32; idx += 256) {
        int d4 = idx >> 5;
        int k  = idx & 31;
        int d0 = d4 * 4;
        float4 w;
        if (k < 16) {
            w.x = W1[(d0 + 0) * H + k];
            w.y = W1[(d0 + 1) * H + k];
            w.z = W1[(d0 + 2) * H + k];
            w.w = W1[(d0 + 3) * H + k];
        } else {
            int kk = k - 16;
            w.x = W1[(D + d0 + 0) * H + kk];
            w.y = W1[(D + d0 + 1) * H + kk];
            w.z = W1[(D + d0 + 2) * H + kk];
            w.w = W1[(D + d0 + 3) * H + kk];
        }
        wt4[idx] = w;
    }

    // Stage up to 128 z rows (coalesced float4)
    {
        const float4* zg = (const float4*)(z + (size_t)nb * D);
        float4* zs4 = (float4*)zs;
        #pragma unroll
        for (int it = 0; it < 16; it++) {
            int idx = it * 256 + tid;             // (row r = idx>>5, d4 = idx&31)
            int r = idx >> 5;
            if (nb + r < N) zs4[idx] = zg[idx];
            else            zs4[idx] = make_float4(0.f, 0.f, 0.f, 0.f);
        }
    }
    __syncthreads();

    const int lane = tid & 31;          // output index k
    const int warp = tid >> 5;
    const int n0   = warp * 16;         // 16 nodes per warp

    unsigned long long acc[16];
    #pragma unroll
    for (int j = 0; j < 16; j++) acc[j] = 0ULL;

    #pragma unroll 4
    for (int d4 = 0; d4 < 32; d4++) {
        float4 w = wt4[d4 * 32 + lane];           // conflict-free
        unsigned long long wlo, whi;
        asm("mov.b64 %0, {%1, %2};" : "=l"(wlo) : "f"(w.x), "f"(w.y));
        asm("mov.b64 %0, {%1, %2};" : "=l"(whi) : "f"(w.z), "f"(w.w));
        #pragma unroll
        for (int j = 0; j < 16; j++) {
            float4 v = ((const float4*)(zs + (n0 + j) * D))[d4];  // broadcast
            unsigned long long vlo, vhi;
            asm("mov.b64 %0, {%1, %2};" : "=l"(vlo) : "f"(v.x), "f"(v.y));
            asm("mov.b64 %0, {%1, %2};" : "=l"(vhi) : "f"(v.z), "f"(v.w));
            asm("fma.rn.f32x2 %0, %1, %2, %0;" : "+l"(acc[j]) : "l"(vlo), "l"(wlo));
            asm("fma.rn.f32x2 %0, %1, %2, %0;" : "+l"(acc[j]) : "l"(vhi), "l"(whi));
        }
    }

    // b1 folded into upper half of P
    float bb = (lane >= 16) ? __ldg(b1 + lane - 16) : 0.f;

    #pragma unroll
    for (int j = 0; j < 16; j++) {
        int n = nb + n0 + j;
        if (n < N) {
            float lo, hi;
            asm("mov.b64 {%0, %1}, %2;" : "=f"(lo), "=f"(hi) : "l"(acc[j]));
            g_P[(size_t)n * 32 + lane] = lo + hi + bb;
        }
    }
}

// ---------------------------------------------------------------------------
// Kernel 2: 8 lanes per edge (4 edges per warp).
//   adj_logits[e] = dot(z[row], z[col])
//   h_j = relu(P[row][j] + P[col][16+j])   (b1 pre-folded)
//   weights[e] = softplus(sum_j h_j * W2[j] + b2)
// out[0:E] = adj_logits, out[E:2E] = weights.  edge_index is int32.
// ---------------------------------------------------------------------------
__global__ __launch_bounds__(256) void edge_kernel(
    const float* __restrict__ z,
    const int* __restrict__ ei,
    const float* __restrict__ W2,
    const float* __restrict__ b2,
    float* __restrict__ out,
    int E)
{
    const int t = blockIdx.x * 256 + threadIdx.x;
    const int e = t >> 3;               // edge id
    const int l = t & 7;                // lane within 8-lane segment
    const bool valid = (e < E);
    const int ec = valid ? e : (E - 1);

    const int row = __ldg(ei + ec);
    const int col = __ldg(ei + (size_t)E + ec);

    // ---- issue all gathers up front ----
    const float4* zr = (const float4*)(z + (size_t)row * D);
    const float4* zc = (const float4*)(z + (size_t)col * D);
    float4 a0 = __ldg(zr + l);
    float4 a1 = __ldg(zr + l + 8);
    float4 a2 = __ldg(zr + l + 16);
    float4 a3 = __ldg(zr + l + 24);
    float4 c0 = __ldg(zc + l);
    float4 c1 = __ldg(zc + l + 8);
    float4 c2 = __ldg(zc + l + 16);
    float4 c3 = __ldg(zc + l + 24);

    float2 pa = *(const float2*)(g_P + (size_t)row * 32 + 2 * l);
    float2 pb = *(const float2*)(g_P + (size_t)col * 32 + 16 + 2 * l);
    float2 w2 = __ldg((const float2*)W2 + l);

    // ---- dot head ----
    float dot = a0.x * c0.x + a0.y * c0.y + a0.z * c0.z + a0.w * c0.w
              + a1.x * c1.x + a1.y * c1.y + a1.z * c1.z + a1.w * c1.w
              + a2.x * c2.x + a2.y * c2.y + a2.z * c2.z + a2.w * c2.w
              + a3.x * c3.x + a3.y * c3.y + a3.z * c3.z + a3.w * c3.w;
    dot += __shfl_xor_sync(0xFFFFFFFFu, dot, 1);
    dot += __shfl_xor_sync(0xFFFFFFFFu, dot, 2);
    dot += __shfl_xor_sync(0xFFFFFFFFu, dot, 4);

    // ---- MLP head ----
    float h0 = fmaxf(pa.x + pb.x, 0.f);
    float h1 = fmaxf(pa.y + pb.y, 0.f);
    float tt = h0 * w2.x + h1 * w2.y;
    tt += __shfl_xor_sync(0xFFFFFFFFu, tt, 1);
    tt += __shfl_xor_sync(0xFFFFFFFFu, tt, 2);
    tt += __shfl_xor_sync(0xFFFFFFFFu, tt, 4);

    if (l == 0 && valid) {
        out[e] = dot;
        float x = tt + __ldg(b2);
        float w = fmaxf(x, 0.f) + log1pf(expf(-fabsf(x)));
        out[(size_t)E + e] = w;
    }
}

extern "C" void kernel_launch(void* const* d_in, const int* in_sizes, int n_in,
                              void* d_out, int out_size)
{
    // metadata order: z, edge_index, W1, b1, W2, b2
    const float* z  = (const float*)d_in[0];
    const int*   ei = (const int*)d_in[1];   // int32
    const float* W1 = (const float*)d_in[2];
    const float* b1 = (const float*)d_in[3];
    const float* W2 = (const float*)d_in[4];
    const float* b2 = (const float*)d_in[5];
    float* out = (float*)d_out;

    const int N = in_sizes[0] / D;      // 100000
    const int E = in_sizes[1] / 2;      // 600000

    const int smem_bytes = (128 * D + 32 * 32 * 4) * 4;   // 80 KB
    static bool attr_set = false;
    if (!attr_set) {
        cudaFuncSetAttribute(proj_kernel,
                             cudaFuncAttributeMaxDynamicSharedMemorySize,
                             smem_bytes);
        attr_set = true;
    }

    proj_kernel<<<(N + 127) / 128, 256, smem_bytes>>>(z, W1, b1, N);

    long long threads = (long long)E * 8;
    int grid = (int)((threads + 255) / 256);
    edge_kernel<<<grid, 256>>>(z, ei, W2, b2, out, E);
}

// round 10
// speedup vs baseline: 2.2535x; 1.0270x over previous
#include <cuda_runtime.h>
#include <cuda_bf16.h>
#include <cstdint>

#define D 128          // feature dim
#define H 16           // hidden dim
#define NMAX 100000    // max nodes (scratch sizing)

// Per-node projections P[n][k]: k in [0,16) = z[n] @ W1[0:128,:],
// k in [16,32) = z[n] @ W1[128:256,:] + b1[k-16]  (b1 folded in).
__device__ float g_P[(size_t)NMAX * 32];

// ---------------------------------------------------------------------------
// Kernel 1: P = [z @ W1a , z @ W1b + b1]
// Block = 256 threads = 8 warps; 128 nodes/block, 16 nodes/warp.
// lane = output k.  W staged as wt4[d4][k] (float4 over d, contiguous in k ->
// conflict-free).  z staged row-major (main-loop reads are uniform
// broadcasts).  Inner product uses packed fma.rn.f32x2 with operands loaded
// DIRECTLY into b64 register pairs via ld.shared.v2.b64 — no mov.b64 packing
// (R9 post-mortem: ptxas does not fold the movs; they doubled issue).
// Dynamic smem: zs 64KB + wt4 16KB = 80KB.
// ---------------------------------------------------------------------------
__global__ __launch_bounds__(256) void proj_kernel(
    const float* __restrict__ z,
    const float* __restrict__ W1,
    const float* __restrict__ b1,
    int N)
{
    extern __shared__ float smem[];
    float*  zs  = smem;                       // [128][128]
    float4* wt4 = (float4*)(smem + 128 * D);  // [32 d4][32 k]

    const int tid = threadIdx.x;
    const int nb  = blockIdx.x * 128;

    // Stage W transposed+vectorized: wt4[d4*32 + k] = (w(k,4d4..4d4+3))
    for (int idx = tid; idx < 32 * 32; idx += 256) {
        int d4 = idx >> 5;
        int k  = idx & 31;
        int d0 = d4 * 4;
        float4 w;
        if (k < 16) {
            w.x = W1[(d0 + 0) * H + k];
            w.y = W1[(d0 + 1) * H + k];
            w.z = W1[(d0 + 2) * H + k];
            w.w = W1[(d0 + 3) * H + k];
        } else {
            int kk = k - 16;
            w.x = W1[(D + d0 + 0) * H + kk];
            w.y = W1[(D + d0 + 1) * H + kk];
            w.z = W1[(D + d0 + 2) * H + kk];
            w.w = W1[(D + d0 + 3) * H + kk];
        }
        wt4[idx] = w;
    }

    // Stage up to 128 z rows (coalesced float4)
    {
        const float4* zg = (const float4*)(z + (size_t)nb * D);
        float4* zs4 = (float4*)zs;
        #pragma unroll
        for (int it = 0; it < 16; it++) {
            int idx = it * 256 + tid;
            int r = idx >> 5;
            if (nb + r < N) zs4[idx] = zg[idx];
            else            zs4[idx] = make_float4(0.f, 0.f, 0.f, 0.f);
        }
    }
    __syncthreads();

    const int lane = tid & 31;          // output index k
    const int warp = tid >> 5;
    const int n0   = warp * 16;         // 16 nodes per warp

    unsigned long long acc[16];
    #pragma unroll
    for (int j = 0; j < 16; j++) acc[j] = 0ULL;

    // 32-bit shared addresses for direct b64-pair loads
    const unsigned int zsh = (unsigned int)__cvta_generic_to_shared(zs + n0 * D);
    const unsigned int wsh = (unsigned int)__cvta_generic_to_shared(wt4) + lane * 16u;

    #pragma unroll 4
    for (int d4 = 0; d4 < 32; d4++) {
        unsigned long long wlo, whi;
        asm("ld.shared.v2.b64 {%0, %1}, [%2];"
            : "=l"(wlo), "=l"(whi) : "r"(wsh + d4 * 512u));   // conflict-free
        #pragma unroll
        for (int j = 0; j < 16; j++) {
            unsigned long long vlo, vhi;
            asm("ld.shared.v2.b64 {%0, %1}, [%2];"
                : "=l"(vlo), "=l"(vhi)
                : "r"(zsh + j * 512u + d4 * 16u));            // broadcast
            asm("fma.rn.f32x2 %0, %1, %2, %0;" : "+l"(acc[j]) : "l"(vlo), "l"(wlo));
            asm("fma.rn.f32x2 %0, %1, %2, %0;" : "+l"(acc[j]) : "l"(vhi), "l"(whi));
        }
    }

    // b1 folded into upper half of P
    float bb = (lane >= 16) ? __ldg(b1 + lane - 16) : 0.f;

    #pragma unroll
    for (int j = 0; j < 16; j++) {
        int n = nb + n0 + j;
        if (n < N) {
            float lo, hi;
            asm("mov.b64 {%0, %1}, %2;" : "=f"(lo), "=f"(hi) : "l"(acc[j]));
            g_P[(size_t)n * 32 + lane] = lo + hi + bb;
        }
    }
}

// ---------------------------------------------------------------------------
// Kernel 2: 8 lanes per edge (4 edges per warp).
//   adj_logits[e] = dot(z[row], z[col])
//   h_j = relu(P[row][j] + P[col][16+j])   (b1 pre-folded)
//   weights[e] = softplus(sum_j h_j * W2[j] + b2)
// out[0:E] = adj_logits, out[E:2E] = weights.  edge_index is int32.
// ---------------------------------------------------------------------------
__global__ __launch_bounds__(256) void edge_kernel(
    const float* __restrict__ z,
    const int* __restrict__ ei,
    const float* __restrict__ W2,
    const float* __restrict__ b2,
    float* __restrict__ out,
    int E)
{
    const int t = blockIdx.x * 256 + threadIdx.x;
    const int e = t >> 3;               // edge id
    const int l = t & 7;                // lane within 8-lane segment
    const bool valid = (e < E);
    const int ec = valid ? e : (E - 1);

    const int row = __ldg(ei + ec);
    const int col = __ldg(ei + (size_t)E + ec);

    // ---- issue all gathers up front ----
    const float4* zr = (const float4*)(z + (size_t)row * D);
    const float4* zc = (const float4*)(z + (size_t)col * D);
    float4 a0 = __ldg(zr + l);
    float4 a1 = __ldg(zr + l + 8);
    float4 a2 = __ldg(zr + l + 16);
    float4 a3 = __ldg(zr + l + 24);
    float4 c0 = __ldg(zc + l);
    float4 c1 = __ldg(zc + l + 8);
    float4 c2 = __ldg(zc + l + 16);
    float4 c3 = __ldg(zc + l + 24);

    float2 pa = *(const float2*)(g_P + (size_t)row * 32 + 2 * l);
    float2 pb = *(const float2*)(g_P + (size_t)col * 32 + 16 + 2 * l);
    float2 w2 = __ldg((const float2*)W2 + l);

    // ---- dot head ----
    float dot = a0.x * c0.x + a0.y * c0.y + a0.z * c0.z + a0.w * c0.w
              + a1.x * c1.x + a1.y * c1.y + a1.z * c1.z + a1.w * c1.w
              + a2.x * c2.x + a2.y * c2.y + a2.z * c2.z + a2.w * c2.w
              + a3.x * c3.x + a3.y * c3.y + a3.z * c3.z + a3.w * c3.w;
    dot += __shfl_xor_sync(0xFFFFFFFFu, dot, 1);
    dot += __shfl_xor_sync(0xFFFFFFFFu, dot, 2);
    dot += __shfl_xor_sync(0xFFFFFFFFu, dot, 4);

    // ---- MLP head ----
    float h0 = fmaxf(pa.x + pb.x, 0.f);
    float h1 = fmaxf(pa.y + pb.y, 0.f);
    float tt = h0 * w2.x + h1 * w2.y;
    tt += __shfl_xor_sync(0xFFFFFFFFu, tt, 1);
    tt += __shfl_xor_sync(0xFFFFFFFFu, tt, 2);
    tt += __shfl_xor_sync(0xFFFFFFFFu, tt, 4);

    if (l == 0 && valid) {
        out[e] = dot;
        float x = tt + __ldg(b2);
        float w = fmaxf(x, 0.f) + log1pf(expf(-fabsf(x)));
        out[(size_t)E + e] = w;
    }
}

extern "C" void kernel_launch(void* const* d_in, const int* in_sizes, int n_in,
                              void* d_out, int out_size)
{
    // metadata order: z, edge_index, W1, b1, W2, b2
    const float* z  = (const float*)d_in[0];
    const int*   ei = (const int*)d_in[1];   // int32
    const float* W1 = (const float*)d_in[2];
    const float* b1 = (const float*)d_in[3];
    const float* W2 = (const float*)d_in[4];
    const float* b2 = (const float*)d_in[5];
    float* out = (float*)d_out;

    const int N = in_sizes[0] / D;      // 100000
    const int E = in_sizes[1] / 2;      // 600000

    const int smem_bytes = (128 * D + 32 * 32 * 4) * 4;   // 80 KB
    static bool attr_set = false;
    if (!attr_set) {
        cudaFuncSetAttribute(proj_kernel,
                             cudaFuncAttributeMaxDynamicSharedMemorySize,
                             smem_bytes);
        attr_set = true;
    }

    proj_kernel<<<(N + 127) / 128, 256, smem_bytes>>>(z, W1, b1, N);

    long long threads = (long long)E * 8;
    int grid = (int)((threads + 255) / 256);
    edge_kernel<<<grid, 256>>>(z, ei, W2, b2, out, E);
}